// round 11
// baseline (speedup 1.0000x reference)
#include <cuda_runtime.h>
#include <cuda_bf16.h>

#define BB 4
#define CC 128
#define HIN 512
#define WIN 512
#define HS 128
#define KPAD 4
#define HP 136            // conv-output spatial size
#define HPP 138           // zero-padded plane dim
#define NPIX (HPP*HPP)    // 19044
#define PROW 19456        // padded plane row (u32 elems), covers window over-reads
#define NG 4
#define CG 32
#define NOFF 81
#define EPSV 1e-8f

typedef unsigned short u16;
typedef unsigned int u32;

// ---------------- scratch ----------------------------------------------------
__device__ u32   g_Ppk[BB*CC*PROW];   // packed bf16 plane: hi | lo<<16
__device__ uint4 g_wK[32*128*16];     // interleaved-K B rows: [step][oc][128 slots]
__device__ float g_xs[BB*CC*HS*HS];   // downsampled x
__device__ float g_yc[BB*CC*HP*HP];   // conv output
__device__ float g_nx[BB*NG*HS*HS];
__device__ float g_ny[BB*NG*HP*HP];

// ---------------- bilinear helpers --------------------------------------------
__device__ __forceinline__ void bilin_coords(int ti, int tj, int& y0, int& x0,
                                             float& fy, float& fx) {
    const double scale = 511.0 / 127.0;
    double py = ti * scale, px = tj * scale;
    y0 = (int)py; x0 = (int)px;
    fy = (float)(py - (double)y0);
    fx = (float)(px - (double)x0);
}
__device__ __forceinline__ float bilin_eval(const float* __restrict__ p,
                                            int y0, int x0, int y1, int x1,
                                            float fy, float fx) {
    float a = p[y0 * WIN + x0], b = p[y0 * WIN + x1];
    float c = p[y1 * WIN + x0], d = p[y1 * WIN + x1];
    float top = a + (b - a) * fx;
    float bot = c + (d - c) * fx;
    return top + (bot - top) * fy;
}

// x-downsample fused over 128 channels + fused group norm nx
__global__ void downsample_x_kernel(const float* __restrict__ x) {
    int idx = blockIdx.x * 256 + threadIdx.x;        // BB*HS*HS threads
    int j = idx & 127, i = (idx >> 7) & 127, b = idx >> 14;
    int y0, x0; float fy, fx;
    bilin_coords(i, j, y0, x0, fy, fx);
    int y1 = min(y0 + 1, 511), x1 = min(x0 + 1, 511);
    float ss[4] = {0.f, 0.f, 0.f, 0.f};
    int px = (i << 7) + j;
    const float* p = x + (size_t)b * CC * HIN * WIN;
    #pragma unroll 4
    for (int c = 0; c < CC; c++) {
        float v = bilin_eval(p + (size_t)c * HIN * WIN, y0, x0, y1, x1, fy, fx);
        g_xs[(((size_t)(b * CC + c)) << 14) + px] = v;
        ss[c >> 5] = fmaf(v, v, ss[c >> 5]);
    }
    #pragma unroll
    for (int g = 0; g < 4; g++)
        g_nx[(((size_t)(b * NG + g)) << 14) + px] = fmaxf(sqrtf(ss[g]), EPSV);
}

// y-downsample + reflect-pad(4) + zero-pad(1), flattened 138x138 plane, bf16 hi/lo
__global__ void make_P_kernel(const float* __restrict__ y) {
    int idx = blockIdx.x * 256 + threadIdx.x;        // BB*PROW threads
    if (idx >= BB * PROW) return;
    int q = idx % PROW, b = idx / PROW;
    bool interior = false;
    int y0 = 0, x0 = 0, y1 = 0, x1 = 0; float fy = 0.f, fx = 0.f;
    if (q < NPIX) {
        int u = q / HPP, w = q % HPP;
        if (u > 0 && u < HPP - 1 && w > 0 && w < HPP - 1) {
            int m = (u - 1) - KPAD; if (m < 0) m = -m; if (m > 127) m = 254 - m;
            int n = (w - 1) - KPAD; if (n < 0) n = -n; if (n > 127) n = 254 - n;
            bilin_coords(m, n, y0, x0, fy, fx);
            y1 = min(y0 + 1, 511); x1 = min(x0 + 1, 511);
            interior = true;
        }
    }
    const float* p = y + (size_t)b * CC * HIN * WIN;
    if (interior) {
        #pragma unroll 4
        for (int c = 0; c < CC; c++) {
            float v = bilin_eval(p + (size_t)c * HIN * WIN, y0, x0, y1, x1, fy, fx);
            __nv_bfloat16 h = __float2bfloat16(v);
            __nv_bfloat16 l = __float2bfloat16(v - __bfloat162float(h));
            g_Ppk[((size_t)(b * CC + c)) * PROW + q] =
                (u32)__bfloat16_as_ushort(h) | ((u32)__bfloat16_as_ushort(l) << 16);
        }
    } else {
        for (int c = 0; c < CC; c++)
            g_Ppk[((size_t)(b * CC + c)) * PROW + q] = 0u;
    }
}

// B rows in interleaved K: step s covers ic = s*4..s*4+3.
// kp = icl*32 + r; r = 3*t + j, tap t = di*3+dj; B slot j: (hi, lo, hi); r>=27 -> 0
__global__ void prep_w_kernel(const float* __restrict__ W) {
    int idx = blockIdx.x * 256 + threadIdx.x;        // 32*128*16
    if (idx >= 32 * 128 * 16) return;
    int unit = idx & 15;
    int oc   = (idx >> 4) & 127;
    int s    = idx >> 11;
    u16 sl[8];
    #pragma unroll
    for (int u = 0; u < 8; u++) {
        int kp = unit * 8 + u, icl = kp >> 5, r = kp & 31;
        u16 val = 0;
        if (r < 27) {
            int t = r / 3, j = r % 3, di = t / 3, dj = t % 3;
            int ic = s * 4 + icl;
            float w = W[((size_t)(oc * CC + ic) * 3 + di) * 3 + dj];
            __nv_bfloat16 h = __float2bfloat16(w);
            if (j == 1)
                val = __bfloat16_as_ushort(__float2bfloat16(w - __bfloat162float(h)));
            else
                val = __bfloat16_as_ushort(h);
        }
        sl[u] = val;
    }
    uint4 qv;
    qv.x = (u32)sl[0] | ((u32)sl[1] << 16);
    qv.y = (u32)sl[2] | ((u32)sl[3] << 16);
    qv.z = (u32)sl[4] | ((u32)sl[5] << 16);
    qv.w = (u32)sl[6] | ((u32)sl[7] << 16);
    g_wK[idx] = qv;
}

// ---------------- tensor-core conv: double-buffered pipelined implicit GEMM ----
// CTA: 128 px x 128 oc, 512 threads (16 warps = 4m x 4n), 1 CTA/SM.
// 32 K-steps of 4 ic; A(s+1)/B(s+1) fetched + built under mma(s); 1 sync/step.
#define APITCH 272                      // bytes per smem row; conflict-free ldsm
#define ABYTES (128*APITCH)             // 34816
#define SM_A0 0
#define SM_A1 ABYTES
#define SM_B0 (2*ABYTES)
#define SM_B1 (3*ABYTES)
#define CONV_SMEM (4*ABYTES)            // 139264 B

__device__ __forceinline__ u32 smem_u32(const void* p) {
    u32 a;
    asm("{ .reg .u64 t; cvta.to.shared.u64 t, %1; cvt.u32.u64 %0, t; }" : "=r"(a) : "l"(p));
    return a;
}
__device__ __forceinline__ void ldsm4(unsigned* r, const void* p) {
    unsigned a = (unsigned)__cvta_generic_to_shared(p);
    asm volatile("ldmatrix.sync.aligned.m8n8.x4.shared.b16 {%0,%1,%2,%3},[%4];"
        : "=r"(r[0]), "=r"(r[1]), "=r"(r[2]), "=r"(r[3]) : "r"(a));
}
__device__ __forceinline__ void mma16816(float* c, const unsigned* a,
                                         unsigned b0, unsigned b1) {
    asm volatile(
        "mma.sync.aligned.m16n8k16.row.col.f32.bf16.bf16.f32 "
        "{%0,%1,%2,%3},{%4,%5,%6,%7},{%8,%9},{%0,%1,%2,%3};"
        : "+f"(c[0]), "+f"(c[1]), "+f"(c[2]), "+f"(c[3])
        : "r"(a[0]), "r"(a[1]), "r"(a[2]), "r"(a[3]), "r"(b0), "r"(b1));
}
__device__ __forceinline__ void cpasync16(u32 dst, const void* src) {
    asm volatile("cp.async.cg.shared.global [%0], [%1], 16;"
                 :: "r"(dst), "l"(src) : "memory");
}

__global__ void __launch_bounds__(512, 1)
conv_mma_kernel(const float* __restrict__ bias) {
    extern __shared__ __align__(16) char sm[];
    u32 smbU = smem_u32(sm);

    int b  = blockIdx.y;
    int p0 = blockIdx.x * 128;
    int tid = threadIdx.x, lane = tid & 31, wid = tid >> 5;
    int wm = wid & 3, wn = wid >> 2;     // 4 m-warps x 4 n-warps

    float acc[2][4][4];
    #pragma unroll
    for (int mt = 0; mt < 2; mt++)
        #pragma unroll
        for (int nt = 0; nt < 4; nt++)
            #pragma unroll
            for (int r = 0; r < 4; r++) acc[mt][nt][r] = 0.f;

    // A-build mapping: one (pixel, ic) per thread
    int am = tid >> 2, icl = tid & 3;
    const u32* prow_base = g_Ppk + (size_t)b * CC * PROW + p0 + am
                         + (size_t)icl * PROW;
    u32 arow_off = (u32)(am * APITCH + icl * 64);

    // B cp.async targets within a B buffer (4 per thread)
    u32 boff[4];
    const uint4* bsrc_base = g_wK;
    #pragma unroll
    for (int e = 0; e < 4; e++) {
        int idx = tid + e * 512;
        boff[e] = (u32)((idx >> 4) * APITCH + (idx & 15) * 16);
    }

    int hi16 = (lane >> 4) << 4;
    int arr  = wm * 32 + (lane & 15);

    // ---- helpers as lambdas ----
    auto gatherA = [&](int s, u32* v) {
        const u32* srow = prow_base + (size_t)(s * 4) * PROW;
        #pragma unroll
        for (int t = 0; t < 9; t++)
            v[t] = srow[(t / 3) * HPP + (t % 3)];
    };
    auto packA = [&](u32 abufU, const u32* v) {
        u16 sl[32];
        #pragma unroll
        for (int i = 27; i < 32; i++) sl[i] = 0;
        #pragma unroll
        for (int t = 0; t < 9; t++) {
            sl[3 * t]     = (u16)v[t];
            sl[3 * t + 1] = (u16)v[t];
            sl[3 * t + 2] = (u16)(v[t] >> 16);
        }
        u32 dst = abufU + arow_off;
        #pragma unroll
        for (int u = 0; u < 4; u++) {
            u32 x0 = (u32)sl[8*u]   | ((u32)sl[8*u+1] << 16);
            u32 x1 = (u32)sl[8*u+2] | ((u32)sl[8*u+3] << 16);
            u32 x2 = (u32)sl[8*u+4] | ((u32)sl[8*u+5] << 16);
            u32 x3 = (u32)sl[8*u+6] | ((u32)sl[8*u+7] << 16);
            asm volatile("st.shared.v4.b32 [%0], {%1,%2,%3,%4};"
                         :: "r"(dst + u * 16), "r"(x0), "r"(x1), "r"(x2), "r"(x3)
                         : "memory");
        }
    };
    auto issueB = [&](int s, u32 bbufU) {
        const uint4* src = bsrc_base + s * 2048;
        #pragma unroll
        for (int e = 0; e < 4; e++)
            cpasync16(bbufU + boff[e], src + tid + e * 512);
        asm volatile("cp.async.commit_group;" ::: "memory");
    };

    // ---- prologue: A(0), B(0) into buf 0 ----
    {
        issueB(0, smbU + SM_B0);
        u32 v[9];
        gatherA(0, v);
        packA(smbU + SM_A0, v);
        asm volatile("cp.async.wait_group 0;" ::: "memory");
        __syncthreads();
    }

    #pragma unroll 1
    for (int s = 0; s < 32; s++) {
        int cb = s & 1, nb = cb ^ 1;
        u32 AsU = smbU + (cb ? SM_A1 : SM_A0);
        const char* Asp = sm + (cb ? SM_A1 : SM_A0);
        const char* Bsp = sm + (cb ? SM_B1 : SM_B0);

        // prefetch next step: B via cp.async, A gather into registers.
        u32 v[9];
        if (s < 31) {
            issueB(s + 1, smbU + (nb ? SM_B1 : SM_B0));
            gatherA(s + 1, v);
        }
        (void)AsU;

        // mma(s): 8 k16 chunks (LDG/cp.async latency drains underneath)
        #pragma unroll 1
        for (int kc = 0; kc < 8; kc++) {
            int colb = kc * 32 + hi16;
            unsigned a0[4], a1[4];
            ldsm4(a0, Asp + arr * APITCH + colb);
            ldsm4(a1, Asp + (arr + 16) * APITCH + colb);
            #pragma unroll
            for (int np = 0; np < 2; np++) {
                int nr = wn * 32 + np * 16 + (lane & 15);
                unsigned bb[4];
                ldsm4(bb, Bsp + nr * APITCH + colb);
                mma16816(acc[0][np*2],   a0, bb[0], bb[2]);
                mma16816(acc[0][np*2+1], a0, bb[1], bb[3]);
                mma16816(acc[1][np*2],   a1, bb[0], bb[2]);
                mma16816(acc[1][np*2+1], a1, bb[1], bb[3]);
            }
        }

        if (s < 31)
            packA(smbU + (nb ? SM_A1 : SM_A0), v);
        asm volatile("cp.async.wait_group 0;" ::: "memory");
        __syncthreads();
    }

    // epilogue: +bias, store planar, fused ny (n-warp wn == norm group)
    int gq = lane >> 2, t = lane & 3;
    #pragma unroll
    for (int mt = 0; mt < 2; mt++) {
        int q0 = p0 + wm * 32 + mt * 16 + gq;      // rows gq and gq+8
        int q1 = q0 + 8;
        int mq0 = q0 / HPP, nq0 = q0 % HPP;
        int mq1 = q1 / HPP, nq1 = q1 % HPP;
        bool v0 = (mq0 < HP) && (nq0 < HP);
        bool v1 = (mq1 < HP) && (nq1 < HP);
        float s0 = 0.f, s1 = 0.f;
        #pragma unroll
        for (int nt = 0; nt < 4; nt++) {
            int oc = wn * 32 + nt * 8 + t * 2;
            float bi0 = __ldg(bias + oc), bi1 = __ldg(bias + oc + 1);
            float a0 = acc[mt][nt][0] + bi0, a1 = acc[mt][nt][1] + bi1;
            float a2 = acc[mt][nt][2] + bi0, a3 = acc[mt][nt][3] + bi1;
            float* base0 = g_yc + (size_t)(b * CC + oc) * HP * HP;
            float* base1 = g_yc + (size_t)(b * CC + oc + 1) * HP * HP;
            if (v0) { base0[mq0 * HP + nq0] = a0; base1[mq0 * HP + nq0] = a1; }
            if (v1) { base0[mq1 * HP + nq1] = a2; base1[mq1 * HP + nq1] = a3; }
            s0 = fmaf(a0, a0, s0); s0 = fmaf(a1, a1, s0);
            s1 = fmaf(a2, a2, s1); s1 = fmaf(a3, a3, s1);
        }
        s0 += __shfl_xor_sync(0xffffffffu, s0, 1);
        s0 += __shfl_xor_sync(0xffffffffu, s0, 2);
        s1 += __shfl_xor_sync(0xffffffffu, s1, 1);
        s1 += __shfl_xor_sync(0xffffffffu, s1, 2);
        if (t == 0) {
            float* nyb = g_ny + (size_t)(b * NG + wn) * HP * HP;
            if (v0) nyb[mq0 * HP + nq0] = sqrtf(s0);
            if (v1) nyb[mq1 * HP + nq1] = sqrtf(s1);
        }
    }
}

// ---------------- 81-offset correlation ------------------------------------------
#define CORR_SY (CG * 16 * 40)
#define CORR_SN (16 * 40)
#define CORR_SMEM ((CORR_SY + CORR_SN) * 4)

__global__ void corr_kernel(float* __restrict__ out) {
    extern __shared__ float smc[];
    float* sy = smc;
    float* sn = smc + CORR_SY;

    int bg = blockIdx.z;
    int b  = bg >> 2, g = bg & 3;
    int i0 = blockIdx.y * 8;
    int j0 = blockIdx.x * 32;
    int tid = threadIdx.x;
    int tj = tid & 31, ti = tid >> 5;

    const float* ycb = g_yc + ((size_t)b * CC + g * CG) * HP * HP;
    for (int e = tid; e < CG * 16 * 40; e += 256) {
        int col = e % 40;
        int row = (e / 40) % 16;
        int c   = e / (16 * 40);
        sy[e] = ycb[(size_t)c * HP * HP + (i0 + row) * HP + (j0 + col)];
    }
    const float* nyb = g_ny + (size_t)bg * HP * HP;
    for (int e = tid; e < 16 * 40; e += 256) {
        int col = e % 40, row = e / 40;
        sn[e] = 1.0f / fmaxf(nyb[(i0 + row) * HP + (j0 + col)], EPSV);
    }
    __syncthreads();

    float xr[CG];
    const float* xsb = g_xs + ((size_t)b * CC + g * CG) * HS * HS
                            + (i0 + ti) * HS + (j0 + tj);
    #pragma unroll
    for (int c = 0; c < CG; c++) xr[c] = xsb[(size_t)c * HS * HS];

    float inx = 1.0f / g_nx[(size_t)bg * HS * HS + (i0 + ti) * HS + (j0 + tj)];
    float* outp = out + (size_t)bg * NOFF * HS * HS + (i0 + ti) * HS + (j0 + tj);

    #pragma unroll 1
    for (int oi = 0; oi < 9; oi++) {
        #pragma unroll 1
        for (int oj = 0; oj < 9; oj++) {
            float a = 0.f;
            int base = (ti + oi) * 40 + tj + oj;
            #pragma unroll
            for (int c = 0; c < CG; c++)
                a = fmaf(xr[c], sy[c * (16 * 40) + base], a);
            outp[(size_t)(oi * 9 + oj) * (HS * HS)] = a * inx * sn[base];
        }
    }
}

// ---------------- launcher --------------------------------------------------------
extern "C" void kernel_launch(void* const* d_in, const int* in_sizes, int n_in,
                              void* d_out, int out_size) {
    const float* x     = (const float*)d_in[0];
    const float* y     = (const float*)d_in[1];
    const float* Wt    = (const float*)d_in[2];
    const float* bconv = (const float*)d_in[3];
    float* out = (float*)d_out;

    cudaFuncSetAttribute(conv_mma_kernel,
                         cudaFuncAttributeMaxDynamicSharedMemorySize, CONV_SMEM);
    cudaFuncSetAttribute(corr_kernel,
                         cudaFuncAttributeMaxDynamicSharedMemorySize, CORR_SMEM);

    downsample_x_kernel<<<(BB*HS*HS) / 256, 256>>>(x);
    make_P_kernel<<<(BB*PROW + 255) / 256, 256>>>(y);
    prep_w_kernel<<<(32*128*16 + 255) / 256, 256>>>(Wt);
    conv_mma_kernel<<<dim3((NPIX + 127) / 128, BB), 512, CONV_SMEM>>>(bconv);
    corr_kernel<<<dim3(4, 16, BB * NG), 256, CORR_SMEM>>>(out);
}

// round 12
// speedup vs baseline: 1.0718x; 1.0718x over previous
#include <cuda_runtime.h>
#include <cuda_bf16.h>

#define BB 4
#define CC 128
#define HIN 512
#define WIN 512
#define HS 128
#define KPAD 4
#define HP 136            // conv-output spatial size
#define HPP 138           // zero-padded plane dim
#define NPIX (HPP*HPP)    // 19044
#define PROW 19456        // padded plane row (u32 elems), covers window over-reads
#define NG 4
#define CG 32
#define NOFF 81
#define EPSV 1e-8f

typedef unsigned short u16;
typedef unsigned int u32;

// ---------------- scratch ----------------------------------------------------
__device__ u32   g_Ppk[BB*CC*PROW];   // packed bf16 plane: hi | lo<<16
__device__ uint4 g_wK[32*128*16];     // interleaved-K B rows: [step][oc][128 slots]
__device__ float g_xs[BB*CC*HS*HS];   // downsampled x
__device__ float g_yc[BB*CC*HP*HP];   // conv output
__device__ float g_nx[BB*NG*HS*HS];
__device__ float g_ny[BB*NG*HP*HP];

// ---------------- bilinear helpers --------------------------------------------
__device__ __forceinline__ void bilin_coords(int ti, int tj, int& y0, int& x0,
                                             float& fy, float& fx) {
    const double scale = 511.0 / 127.0;
    double py = ti * scale, px = tj * scale;
    y0 = (int)py; x0 = (int)px;
    fy = (float)(py - (double)y0);
    fx = (float)(px - (double)x0);
}
__device__ __forceinline__ float bilin_eval(const float* __restrict__ p,
                                            int y0, int x0, int y1, int x1,
                                            float fy, float fx) {
    float a = p[y0 * WIN + x0], b = p[y0 * WIN + x1];
    float c = p[y1 * WIN + x0], d = p[y1 * WIN + x1];
    float top = a + (b - a) * fx;
    float bot = c + (d - c) * fx;
    return top + (bot - top) * fy;
}

// x-downsample fused over 128 channels + fused group norm nx
__global__ void downsample_x_kernel(const float* __restrict__ x) {
    int idx = blockIdx.x * 256 + threadIdx.x;        // BB*HS*HS threads
    int j = idx & 127, i = (idx >> 7) & 127, b = idx >> 14;
    int y0, x0; float fy, fx;
    bilin_coords(i, j, y0, x0, fy, fx);
    int y1 = min(y0 + 1, 511), x1 = min(x0 + 1, 511);
    float ss[4] = {0.f, 0.f, 0.f, 0.f};
    int px = (i << 7) + j;
    const float* p = x + (size_t)b * CC * HIN * WIN;
    #pragma unroll 4
    for (int c = 0; c < CC; c++) {
        float v = bilin_eval(p + (size_t)c * HIN * WIN, y0, x0, y1, x1, fy, fx);
        g_xs[(((size_t)(b * CC + c)) << 14) + px] = v;
        ss[c >> 5] = fmaf(v, v, ss[c >> 5]);
    }
    #pragma unroll
    for (int g = 0; g < 4; g++)
        g_nx[(((size_t)(b * NG + g)) << 14) + px] = fmaxf(sqrtf(ss[g]), EPSV);
}

// y-downsample + reflect-pad(4) + zero-pad(1), flattened 138x138 plane, bf16 hi/lo
__global__ void make_P_kernel(const float* __restrict__ y) {
    int idx = blockIdx.x * 256 + threadIdx.x;        // BB*PROW threads
    if (idx >= BB * PROW) return;
    int q = idx % PROW, b = idx / PROW;
    bool interior = false;
    int y0 = 0, x0 = 0, y1 = 0, x1 = 0; float fy = 0.f, fx = 0.f;
    if (q < NPIX) {
        int u = q / HPP, w = q % HPP;
        if (u > 0 && u < HPP - 1 && w > 0 && w < HPP - 1) {
            int m = (u - 1) - KPAD; if (m < 0) m = -m; if (m > 127) m = 254 - m;
            int n = (w - 1) - KPAD; if (n < 0) n = -n; if (n > 127) n = 254 - n;
            bilin_coords(m, n, y0, x0, fy, fx);
            y1 = min(y0 + 1, 511); x1 = min(x0 + 1, 511);
            interior = true;
        }
    }
    const float* p = y + (size_t)b * CC * HIN * WIN;
    if (interior) {
        #pragma unroll 4
        for (int c = 0; c < CC; c++) {
            float v = bilin_eval(p + (size_t)c * HIN * WIN, y0, x0, y1, x1, fy, fx);
            __nv_bfloat16 h = __float2bfloat16(v);
            __nv_bfloat16 l = __float2bfloat16(v - __bfloat162float(h));
            g_Ppk[((size_t)(b * CC + c)) * PROW + q] =
                (u32)__bfloat16_as_ushort(h) | ((u32)__bfloat16_as_ushort(l) << 16);
        }
    } else {
        for (int c = 0; c < CC; c++)
            g_Ppk[((size_t)(b * CC + c)) * PROW + q] = 0u;
    }
}

// B rows in interleaved K: step s covers ic = s*4..s*4+3.
// kp = icl*32 + r; r = 3*t + j, tap t = di*3+dj; B slot j: (hi, lo, hi); r>=27 -> 0
__global__ void prep_w_kernel(const float* __restrict__ W) {
    int idx = blockIdx.x * 256 + threadIdx.x;        // 32*128*16
    if (idx >= 32 * 128 * 16) return;
    int unit = idx & 15;
    int oc   = (idx >> 4) & 127;
    int s    = idx >> 11;
    u16 sl[8];
    #pragma unroll
    for (int u = 0; u < 8; u++) {
        int kp = unit * 8 + u, icl = kp >> 5, r = kp & 31;
        u16 val = 0;
        if (r < 27) {
            int t = r / 3, j = r % 3, di = t / 3, dj = t % 3;
            int ic = s * 4 + icl;
            float w = W[((size_t)(oc * CC + ic) * 3 + di) * 3 + dj];
            __nv_bfloat16 h = __float2bfloat16(w);
            if (j == 1)
                val = __bfloat16_as_ushort(__float2bfloat16(w - __bfloat162float(h)));
            else
                val = __bfloat16_as_ushort(h);
        }
        sl[u] = val;
    }
    uint4 qv;
    qv.x = (u32)sl[0] | ((u32)sl[1] << 16);
    qv.y = (u32)sl[2] | ((u32)sl[3] << 16);
    qv.z = (u32)sl[4] | ((u32)sl[5] << 16);
    qv.w = (u32)sl[6] | ((u32)sl[7] << 16);
    g_wK[idx] = qv;
}

// ---------------- tensor-core conv: interleaved-K implicit GEMM (R10) ----------
#define APITCH 272                      // bytes per smem row; conflict-free ldsm
#define SM_A 0
#define SM_B (128*APITCH)
#define CONV_SMEM (2*128*APITCH)        // 69632 B

__device__ __forceinline__ u32 smem_u32(const void* p) {
    u32 a;
    asm("{ .reg .u64 t; cvta.to.shared.u64 t, %1; cvt.u32.u64 %0, t; }" : "=r"(a) : "l"(p));
    return a;
}
__device__ __forceinline__ void ldsm4(unsigned* r, const void* p) {
    unsigned a = (unsigned)__cvta_generic_to_shared(p);
    asm volatile("ldmatrix.sync.aligned.m8n8.x4.shared.b16 {%0,%1,%2,%3},[%4];"
        : "=r"(r[0]), "=r"(r[1]), "=r"(r[2]), "=r"(r[3]) : "r"(a));
}
__device__ __forceinline__ void mma16816(float* c, const unsigned* a,
                                         unsigned b0, unsigned b1) {
    asm volatile(
        "mma.sync.aligned.m16n8k16.row.col.f32.bf16.bf16.f32 "
        "{%0,%1,%2,%3},{%4,%5,%6,%7},{%8,%9},{%0,%1,%2,%3};"
        : "+f"(c[0]), "+f"(c[1]), "+f"(c[2]), "+f"(c[3])
        : "r"(a[0]), "r"(a[1]), "r"(a[2]), "r"(a[3]), "r"(b0), "r"(b1));
}
__device__ __forceinline__ void cpasync16(u32 dst, const void* src) {
    asm volatile("cp.async.cg.shared.global [%0], [%1], 16;"
                 :: "r"(dst), "l"(src) : "memory");
}

__global__ void __launch_bounds__(256, 2)
conv_mma_kernel(const float* __restrict__ bias) {
    extern __shared__ __align__(16) char sm[];
    char* As = sm + SM_A;
    char* Bs = sm + SM_B;
    u32 BsU = smem_u32(Bs);

    int b  = blockIdx.y;
    int p0 = blockIdx.x * 128;
    int tid = threadIdx.x, lane = tid & 31, wid = tid >> 5;
    int wm = wid & 3, wn = wid >> 2;     // 4 m-warps x 2 n-warps

    float acc[2][8][4];
    #pragma unroll
    for (int mt = 0; mt < 2; mt++)
        #pragma unroll
        for (int nt = 0; nt < 8; nt++)
            #pragma unroll
            for (int r = 0; r < 4; r++) acc[mt][nt][r] = 0.f;

    int am = tid >> 1;                   // A-build pixel row (0..127)
    const u32* prow_base = g_Ppk + (size_t)b * CC * PROW + p0 + am;

    u32 bdst[8];
    #pragma unroll
    for (int e = 0; e < 8; e++) {
        int idx = tid + e * 256;
        bdst[e] = BsU + (idx >> 4) * APITCH + (idx & 15) * 16;
    }

    #pragma unroll 1
    for (int s = 0; s < 32; s++) {
        __syncthreads();
        {
            const uint4* src = g_wK + s * 2048;
            #pragma unroll
            for (int e = 0; e < 8; e++)
                cpasync16(bdst[e], src + tid + e * 256);
            asm volatile("cp.async.commit_group;" ::: "memory");
        }
        #pragma unroll
        for (int ii = 0; ii < 2; ii++) {
            int icl = (tid & 1) * 2 + ii;
            const u32* srow = prow_base + (size_t)(s * 4 + icl) * PROW;
            u16 sl[32];
            #pragma unroll
            for (int i = 27; i < 32; i++) sl[i] = 0;
            #pragma unroll
            for (int t = 0; t < 9; t++) {
                u32 v = srow[(t / 3) * HPP + (t % 3)];
                sl[3 * t]     = (u16)v;
                sl[3 * t + 1] = (u16)v;
                sl[3 * t + 2] = (u16)(v >> 16);
            }
            char* arow = As + am * APITCH + icl * 64;
            #pragma unroll
            for (int u = 0; u < 4; u++) {
                uint4 qv;
                qv.x = (u32)sl[8*u]   | ((u32)sl[8*u+1] << 16);
                qv.y = (u32)sl[8*u+2] | ((u32)sl[8*u+3] << 16);
                qv.z = (u32)sl[8*u+4] | ((u32)sl[8*u+5] << 16);
                qv.w = (u32)sl[8*u+6] | ((u32)sl[8*u+7] << 16);
                *(uint4*)(arow + u * 16) = qv;
            }
        }
        asm volatile("cp.async.wait_group 0;" ::: "memory");
        __syncthreads();

        #pragma unroll 1
        for (int kc = 0; kc < 8; kc++) {
            int colb = kc * 32 + ((lane >> 4) << 4);
            int ar   = wm * 32 + (lane & 15);
            unsigned a0[4], a1[4];
            ldsm4(a0, As + ar * APITCH + colb);
            ldsm4(a1, As + (ar + 16) * APITCH + colb);
            #pragma unroll
            for (int np = 0; np < 4; np++) {
                int nr = wn * 64 + np * 16 + (lane & 15);
                unsigned bb[4];
                ldsm4(bb, Bs + nr * APITCH + colb);
                mma16816(acc[0][np*2],   a0, bb[0], bb[2]);
                mma16816(acc[0][np*2+1], a0, bb[1], bb[3]);
                mma16816(acc[1][np*2],   a1, bb[0], bb[2]);
                mma16816(acc[1][np*2+1], a1, bb[1], bb[3]);
            }
        }
    }

    int gq = lane >> 2, t = lane & 3;
    #pragma unroll
    for (int mt = 0; mt < 2; mt++) {
        int q0 = p0 + wm * 32 + mt * 16 + gq;
        int q1 = q0 + 8;
        int mq0 = q0 / HPP, nq0 = q0 % HPP;
        int mq1 = q1 / HPP, nq1 = q1 % HPP;
        bool v0 = (mq0 < HP) && (nq0 < HP);
        bool v1 = (mq1 < HP) && (nq1 < HP);
        float s00 = 0.f, s01 = 0.f, s10 = 0.f, s11 = 0.f;
        #pragma unroll
        for (int nt = 0; nt < 8; nt++) {
            int oc = wn * 64 + nt * 8 + t * 2;
            float bi0 = __ldg(bias + oc), bi1 = __ldg(bias + oc + 1);
            float a0 = acc[mt][nt][0] + bi0, a1 = acc[mt][nt][1] + bi1;
            float a2 = acc[mt][nt][2] + bi0, a3 = acc[mt][nt][3] + bi1;
            float* base0 = g_yc + (size_t)(b * CC + oc) * HP * HP;
            float* base1 = g_yc + (size_t)(b * CC + oc + 1) * HP * HP;
            if (v0) { base0[mq0 * HP + nq0] = a0; base1[mq0 * HP + nq0] = a1; }
            if (v1) { base0[mq1 * HP + nq1] = a2; base1[mq1 * HP + nq1] = a3; }
            if (nt < 4) {
                s00 = fmaf(a0, a0, s00); s00 = fmaf(a1, a1, s00);
                s10 = fmaf(a2, a2, s10); s10 = fmaf(a3, a3, s10);
            } else {
                s01 = fmaf(a0, a0, s01); s01 = fmaf(a1, a1, s01);
                s11 = fmaf(a2, a2, s11); s11 = fmaf(a3, a3, s11);
            }
        }
        s00 += __shfl_xor_sync(0xffffffffu, s00, 1);
        s00 += __shfl_xor_sync(0xffffffffu, s00, 2);
        s01 += __shfl_xor_sync(0xffffffffu, s01, 1);
        s01 += __shfl_xor_sync(0xffffffffu, s01, 2);
        s10 += __shfl_xor_sync(0xffffffffu, s10, 1);
        s10 += __shfl_xor_sync(0xffffffffu, s10, 2);
        s11 += __shfl_xor_sync(0xffffffffu, s11, 1);
        s11 += __shfl_xor_sync(0xffffffffu, s11, 2);
        if (t == 0) {
            float* ny0 = g_ny + (size_t)(b * NG + wn * 2) * HP * HP;
            float* ny1 = g_ny + (size_t)(b * NG + wn * 2 + 1) * HP * HP;
            if (v0) { ny0[mq0 * HP + nq0] = sqrtf(s00); ny1[mq0 * HP + nq0] = sqrtf(s01); }
            if (v1) { ny0[mq1 * HP + nq1] = sqrtf(s10); ny1[mq1 * HP + nq1] = sqrtf(s11); }
        }
    }
}

// ---------------- 81-offset correlation: 4-px register blocking ------------------
// Block: (b,g) x 8h x 32w tile, 256 threads = 64 positions x 4 channel slices.
// Thread: 4 adjacent px, 8 channels (c = 4*cc + slice), 3 aligned LDS.128 per
// (c, oi) row serve 36 FMAs. Cross-slice shfl.xor butterfly per output.
#define CSTRIDE 648                     // floats per channel block (162 chunks = 2 mod 8)
#define CORR_SY (CG * CSTRIDE)          // 20736 floats
#define CORR_SN (16 * 40)
#define CORR_SMEM ((CORR_SY + CORR_SN) * 4)   // 85504 B

__global__ void __launch_bounds__(256, 2)
corr_kernel(float* __restrict__ out) {
    extern __shared__ float smc[];
    float* sy = smc;                    // [c][row*40+col], channel stride 648
    float* sn = smc + CORR_SY;          // reciprocal norms, pitch 40

    int bg = blockIdx.z;
    int b  = bg >> 2, g = bg & 3;
    int i0 = blockIdx.y * 8;
    int j0 = blockIdx.x * 32;
    int tid = threadIdx.x;

    // fill sy (coalesced per (c,row))
    const float* ycb = g_yc + ((size_t)b * CC + g * CG) * HP * HP;
    for (int e = tid; e < CG * 16 * 40; e += 256) {
        int col = e % 40;
        int row = (e / 40) % 16;
        int c   = e / 640;
        sy[c * CSTRIDE + row * 40 + col] =
            ycb[(size_t)c * HP * HP + (i0 + row) * HP + (j0 + col)];
    }
    const float* nyb = g_ny + (size_t)bg * HP * HP;
    for (int e = tid; e < 16 * 40; e += 256) {
        int col = e % 40, row = e / 40;
        sn[e] = 1.0f / fmaxf(nyb[(i0 + row) * HP + (j0 + col)], EPSV);
    }
    __syncthreads();

    int sl  = tid & 3;                  // channel slice
    int pos = tid >> 2;                 // 0..63
    int ti  = pos >> 3;                 // 0..7 pixel row
    int tj4 = (pos & 7) * 4;            // col quad

    // x regs: 8 channels (4*cc+sl) x 4 px
    float4 xv[8];
    const float* xsb = g_xs + ((size_t)(b * CC + g * CG + sl)) * (HS * HS)
                            + (i0 + ti) * HS + (j0 + tj4);
    #pragma unroll
    for (int cc = 0; cc < 8; cc++)
        xv[cc] = *(const float4*)(xsb + (size_t)(cc * 4) * HS * HS);

    // 1/nx for the 4 px
    float4 nx4 = *(const float4*)(g_nx + (size_t)bg * HS * HS
                                  + (i0 + ti) * HS + (j0 + tj4));
    float inx[4] = {1.0f / nx4.x, 1.0f / nx4.y, 1.0f / nx4.z, 1.0f / nx4.w};

    float* outp = out + (size_t)bg * NOFF * (HS * HS)
                      + (i0 + ti) * HS + (j0 + tj4);

    #pragma unroll 1
    for (int oi = 0; oi < 9; oi++) {
        float acc[9][4];
        #pragma unroll
        for (int oj = 0; oj < 9; oj++)
            #pragma unroll
            for (int p = 0; p < 4; p++) acc[oj][p] = 0.f;

        #pragma unroll
        for (int cc = 0; cc < 8; cc++) {
            const float* rp = sy + (4 * cc + sl) * CSTRIDE + (ti + oi) * 40 + tj4;
            float4 v0 = *(const float4*)(rp);
            float4 v1 = *(const float4*)(rp + 4);
            float4 v2 = *(const float4*)(rp + 8);
            float v[12] = {v0.x, v0.y, v0.z, v0.w, v1.x, v1.y, v1.z, v1.w,
                           v2.x, v2.y, v2.z, v2.w};
            float xp[4] = {xv[cc].x, xv[cc].y, xv[cc].z, xv[cc].w};
            #pragma unroll
            for (int oj = 0; oj < 9; oj++)
                #pragma unroll
                for (int p = 0; p < 4; p++)
                    acc[oj][p] = fmaf(xp[p], v[oj + p], acc[oj][p]);
        }

        // reduce across the 4 slices (lanes differing in bits 0,1)
        #pragma unroll
        for (int oj = 0; oj < 9; oj++)
            #pragma unroll
            for (int p = 0; p < 4; p++) {
                float sv = acc[oj][p];
                sv += __shfl_xor_sync(0xffffffffu, sv, 1);
                sv += __shfl_xor_sync(0xffffffffu, sv, 2);
                acc[oj][p] = sv;
            }

        if (sl == 0) {
            const float* np_ = sn + (ti + oi) * 40 + tj4;
            float nv[12];
            #pragma unroll
            for (int q = 0; q < 3; q++) {
                float4 t4 = *(const float4*)(np_ + q * 4);
                nv[q*4] = t4.x; nv[q*4+1] = t4.y; nv[q*4+2] = t4.z; nv[q*4+3] = t4.w;
            }
            #pragma unroll
            for (int oj = 0; oj < 9; oj++) {
                float4 o4;
                o4.x = acc[oj][0] * inx[0] * nv[oj + 0];
                o4.y = acc[oj][1] * inx[1] * nv[oj + 1];
                o4.z = acc[oj][2] * inx[2] * nv[oj + 2];
                o4.w = acc[oj][3] * inx[3] * nv[oj + 3];
                *(float4*)(outp + (size_t)(oi * 9 + oj) * (HS * HS)) = o4;
            }
        }
    }
}

// ---------------- launcher --------------------------------------------------------
extern "C" void kernel_launch(void* const* d_in, const int* in_sizes, int n_in,
                              void* d_out, int out_size) {
    const float* x     = (const float*)d_in[0];
    const float* y     = (const float*)d_in[1];
    const float* Wt    = (const float*)d_in[2];
    const float* bconv = (const float*)d_in[3];
    float* out = (float*)d_out;

    cudaFuncSetAttribute(conv_mma_kernel,
                         cudaFuncAttributeMaxDynamicSharedMemorySize, CONV_SMEM);
    cudaFuncSetAttribute(corr_kernel,
                         cudaFuncAttributeMaxDynamicSharedMemorySize, CORR_SMEM);

    downsample_x_kernel<<<(BB*HS*HS) / 256, 256>>>(x);
    make_P_kernel<<<(BB*PROW + 255) / 256, 256>>>(y);
    prep_w_kernel<<<(32*128*16 + 255) / 256, 256>>>(Wt);
    conv_mma_kernel<<<dim3((NPIX + 127) / 128, BB), 256, CONV_SMEM>>>(bconv);
    corr_kernel<<<dim3(4, 16, BB * NG), 256, CORR_SMEM>>>(out);
}

// round 13
// speedup vs baseline: 1.1616x; 1.0837x over previous
#include <cuda_runtime.h>
#include <cuda_bf16.h>

#define BB 4
#define CC 128
#define HIN 512
#define WIN 512
#define HS 128
#define KPAD 4
#define HP 136            // conv-output spatial size
#define HPP 138           // zero-padded plane dim
#define NPIX (HPP*HPP)    // 19044
#define PROW 19456        // padded plane row (u32 elems), covers window over-reads
#define NG 4
#define CG 32
#define NOFF 81
#define EPSV 1e-8f

typedef unsigned short u16;
typedef unsigned int u32;

// ---------------- scratch ----------------------------------------------------
__device__ u32   g_Ppk[BB*CC*PROW];   // packed bf16 plane: hi | lo<<16
__device__ uint4 g_wK[32*128*16];     // interleaved-K B rows: [step][oc][128 slots]
__device__ float g_xs[BB*CC*HS*HS];   // downsampled x
__device__ float g_yc[BB*CC*HP*HP];   // conv output
__device__ float g_nx[BB*NG*HS*HS];
__device__ float g_ny[BB*NG*HP*HP];

// ---------------- bilinear helpers --------------------------------------------
__device__ __forceinline__ void bilin_coords(int ti, int tj, int& y0, int& x0,
                                             float& fy, float& fx) {
    const double scale = 511.0 / 127.0;
    double py = ti * scale, px = tj * scale;
    y0 = (int)py; x0 = (int)px;
    fy = (float)(py - (double)y0);
    fx = (float)(px - (double)x0);
}
__device__ __forceinline__ float bilin_eval(const float* __restrict__ p,
                                            int y0, int x0, int y1, int x1,
                                            float fy, float fx) {
    float a = p[y0 * WIN + x0], b = p[y0 * WIN + x1];
    float c = p[y1 * WIN + x0], d = p[y1 * WIN + x1];
    float top = a + (b - a) * fx;
    float bot = c + (d - c) * fx;
    return top + (bot - top) * fy;
}

// x-downsample: one thread per (b, group, i, j); 32 channels + fused nx
__global__ void downsample_x_kernel(const float* __restrict__ x) {
    int idx = blockIdx.x * 256 + threadIdx.x;        // BB*4*HS*HS threads
    int j  = idx & 127;
    int i  = (idx >> 7) & 127;
    int cq = (idx >> 14) & 3;
    int b  = idx >> 16;
    int y0, x0; float fy, fx;
    bilin_coords(i, j, y0, x0, fy, fx);
    int y1 = min(y0 + 1, 511), x1 = min(x0 + 1, 511);
    float ss = 0.f;
    int px = (i << 7) + j;
    const float* p = x + (size_t)(b * CC + cq * CG) * HIN * WIN;
    float* xo = g_xs + (((size_t)(b * CC + cq * CG)) << 14) + px;
    #pragma unroll 8
    for (int c = 0; c < CG; c++) {
        float v = bilin_eval(p + (size_t)c * HIN * WIN, y0, x0, y1, x1, fy, fx);
        xo[(size_t)c << 14] = v;
        ss = fmaf(v, v, ss);
    }
    g_nx[(((size_t)(b * NG + cq)) << 14) + px] = fmaxf(sqrtf(ss), EPSV);
}

// y-downsample + reflect-pad(4) + zero-pad(1), flattened plane, bf16 hi/lo;
// one thread per (b, group, q): 32 channels
__global__ void make_P_kernel(const float* __restrict__ y) {
    int idx = blockIdx.x * 256 + threadIdx.x;        // BB*4*PROW threads
    if (idx >= BB * 4 * PROW) return;
    int q    = idx % PROW;
    int rest = idx / PROW;
    int cq = rest & 3, b = rest >> 2;
    bool interior = false;
    int y0 = 0, x0 = 0, y1 = 0, x1 = 0; float fy = 0.f, fx = 0.f;
    if (q < NPIX) {
        int u = q / HPP, w = q % HPP;
        if (u > 0 && u < HPP - 1 && w > 0 && w < HPP - 1) {
            int m = (u - 1) - KPAD; if (m < 0) m = -m; if (m > 127) m = 254 - m;
            int n = (w - 1) - KPAD; if (n < 0) n = -n; if (n > 127) n = 254 - n;
            bilin_coords(m, n, y0, x0, fy, fx);
            y1 = min(y0 + 1, 511); x1 = min(x0 + 1, 511);
            interior = true;
        }
    }
    const float* p = y + (size_t)(b * CC + cq * CG) * HIN * WIN;
    u32* po = g_Ppk + ((size_t)(b * CC + cq * CG)) * PROW + q;
    if (interior) {
        #pragma unroll 8
        for (int c = 0; c < CG; c++) {
            float v = bilin_eval(p + (size_t)c * HIN * WIN, y0, x0, y1, x1, fy, fx);
            __nv_bfloat16 h = __float2bfloat16(v);
            __nv_bfloat16 l = __float2bfloat16(v - __bfloat162float(h));
            po[(size_t)c * PROW] =
                (u32)__bfloat16_as_ushort(h) | ((u32)__bfloat16_as_ushort(l) << 16);
        }
    } else {
        #pragma unroll 8
        for (int c = 0; c < CG; c++)
            po[(size_t)c * PROW] = 0u;
    }
}

// B rows in interleaved K: step s covers ic = s*4..s*4+3.
// kp = icl*32 + r; r = 3*t + j, tap t = di*3+dj; B slot j: (hi, lo, hi); r>=27 -> 0
__global__ void prep_w_kernel(const float* __restrict__ W) {
    int idx = blockIdx.x * 256 + threadIdx.x;        // 32*128*16
    if (idx >= 32 * 128 * 16) return;
    int unit = idx & 15;
    int oc   = (idx >> 4) & 127;
    int s    = idx >> 11;
    u16 sl[8];
    #pragma unroll
    for (int u = 0; u < 8; u++) {
        int kp = unit * 8 + u, icl = kp >> 5, r = kp & 31;
        u16 val = 0;
        if (r < 27) {
            int t = r / 3, j = r % 3, di = t / 3, dj = t % 3;
            int ic = s * 4 + icl;
            float w = W[((size_t)(oc * CC + ic) * 3 + di) * 3 + dj];
            __nv_bfloat16 h = __float2bfloat16(w);
            if (j == 1)
                val = __bfloat16_as_ushort(__float2bfloat16(w - __bfloat162float(h)));
            else
                val = __bfloat16_as_ushort(h);
        }
        sl[u] = val;
    }
    uint4 qv;
    qv.x = (u32)sl[0] | ((u32)sl[1] << 16);
    qv.y = (u32)sl[2] | ((u32)sl[3] << 16);
    qv.z = (u32)sl[4] | ((u32)sl[5] << 16);
    qv.w = (u32)sl[6] | ((u32)sl[7] << 16);
    g_wK[idx] = qv;
}

// ---------------- tensor-core conv: interleaved-K implicit GEMM (R10) ----------
#define APITCH 272                      // bytes per smem row; conflict-free ldsm
#define SM_A 0
#define SM_B (128*APITCH)
#define CONV_SMEM (2*128*APITCH)        // 69632 B

__device__ __forceinline__ u32 smem_u32(const void* p) {
    u32 a;
    asm("{ .reg .u64 t; cvta.to.shared.u64 t, %1; cvt.u32.u64 %0, t; }" : "=r"(a) : "l"(p));
    return a;
}
__device__ __forceinline__ void ldsm4(unsigned* r, const void* p) {
    unsigned a = (unsigned)__cvta_generic_to_shared(p);
    asm volatile("ldmatrix.sync.aligned.m8n8.x4.shared.b16 {%0,%1,%2,%3},[%4];"
        : "=r"(r[0]), "=r"(r[1]), "=r"(r[2]), "=r"(r[3]) : "r"(a));
}
__device__ __forceinline__ void mma16816(float* c, const unsigned* a,
                                         unsigned b0, unsigned b1) {
    asm volatile(
        "mma.sync.aligned.m16n8k16.row.col.f32.bf16.bf16.f32 "
        "{%0,%1,%2,%3},{%4,%5,%6,%7},{%8,%9},{%0,%1,%2,%3};"
        : "+f"(c[0]), "+f"(c[1]), "+f"(c[2]), "+f"(c[3])
        : "r"(a[0]), "r"(a[1]), "r"(a[2]), "r"(a[3]), "r"(b0), "r"(b1));
}
__device__ __forceinline__ void cpasync16(u32 dst, const void* src) {
    asm volatile("cp.async.cg.shared.global [%0], [%1], 16;"
                 :: "r"(dst), "l"(src) : "memory");
}

__global__ void __launch_bounds__(256, 2)
conv_mma_kernel(const float* __restrict__ bias) {
    extern __shared__ __align__(16) char sm[];
    char* As = sm + SM_A;
    char* Bs = sm + SM_B;
    u32 BsU = smem_u32(Bs);

    int b  = blockIdx.y;
    int p0 = blockIdx.x * 128;
    int tid = threadIdx.x, lane = tid & 31, wid = tid >> 5;
    int wm = wid & 3, wn = wid >> 2;     // 4 m-warps x 2 n-warps

    float acc[2][8][4];
    #pragma unroll
    for (int mt = 0; mt < 2; mt++)
        #pragma unroll
        for (int nt = 0; nt < 8; nt++)
            #pragma unroll
            for (int r = 0; r < 4; r++) acc[mt][nt][r] = 0.f;

    int am = tid >> 1;                   // A-build pixel row (0..127)
    const u32* prow_base = g_Ppk + (size_t)b * CC * PROW + p0 + am;

    u32 bdst[8];
    #pragma unroll
    for (int e = 0; e < 8; e++) {
        int idx = tid + e * 256;
        bdst[e] = BsU + (idx >> 4) * APITCH + (idx & 15) * 16;
    }

    #pragma unroll 1
    for (int s = 0; s < 32; s++) {
        __syncthreads();
        {
            const uint4* src = g_wK + s * 2048;
            #pragma unroll
            for (int e = 0; e < 8; e++)
                cpasync16(bdst[e], src + tid + e * 256);
            asm volatile("cp.async.commit_group;" ::: "memory");
        }
        #pragma unroll
        for (int ii = 0; ii < 2; ii++) {
            int icl = (tid & 1) * 2 + ii;
            const u32* srow = prow_base + (size_t)(s * 4 + icl) * PROW;
            u16 sl[32];
            #pragma unroll
            for (int i = 27; i < 32; i++) sl[i] = 0;
            #pragma unroll
            for (int t = 0; t < 9; t++) {
                u32 v = srow[(t / 3) * HPP + (t % 3)];
                sl[3 * t]     = (u16)v;
                sl[3 * t + 1] = (u16)v;
                sl[3 * t + 2] = (u16)(v >> 16);
            }
            char* arow = As + am * APITCH + icl * 64;
            #pragma unroll
            for (int u = 0; u < 4; u++) {
                uint4 qv;
                qv.x = (u32)sl[8*u]   | ((u32)sl[8*u+1] << 16);
                qv.y = (u32)sl[8*u+2] | ((u32)sl[8*u+3] << 16);
                qv.z = (u32)sl[8*u+4] | ((u32)sl[8*u+5] << 16);
                qv.w = (u32)sl[8*u+6] | ((u32)sl[8*u+7] << 16);
                *(uint4*)(arow + u * 16) = qv;
            }
        }
        asm volatile("cp.async.wait_group 0;" ::: "memory");
        __syncthreads();

        #pragma unroll 1
        for (int kc = 0; kc < 8; kc++) {
            int colb = kc * 32 + ((lane >> 4) << 4);
            int ar   = wm * 32 + (lane & 15);
            unsigned a0[4], a1[4];
            ldsm4(a0, As + ar * APITCH + colb);
            ldsm4(a1, As + (ar + 16) * APITCH + colb);
            #pragma unroll
            for (int np = 0; np < 4; np++) {
                int nr = wn * 64 + np * 16 + (lane & 15);
                unsigned bb[4];
                ldsm4(bb, Bs + nr * APITCH + colb);
                mma16816(acc[0][np*2],   a0, bb[0], bb[2]);
                mma16816(acc[0][np*2+1], a0, bb[1], bb[3]);
                mma16816(acc[1][np*2],   a1, bb[0], bb[2]);
                mma16816(acc[1][np*2+1], a1, bb[1], bb[3]);
            }
        }
    }

    int gq = lane >> 2, t = lane & 3;
    #pragma unroll
    for (int mt = 0; mt < 2; mt++) {
        int q0 = p0 + wm * 32 + mt * 16 + gq;
        int q1 = q0 + 8;
        int mq0 = q0 / HPP, nq0 = q0 % HPP;
        int mq1 = q1 / HPP, nq1 = q1 % HPP;
        bool v0 = (mq0 < HP) && (nq0 < HP);
        bool v1 = (mq1 < HP) && (nq1 < HP);
        float s00 = 0.f, s01 = 0.f, s10 = 0.f, s11 = 0.f;
        #pragma unroll
        for (int nt = 0; nt < 8; nt++) {
            int oc = wn * 64 + nt * 8 + t * 2;
            float bi0 = __ldg(bias + oc), bi1 = __ldg(bias + oc + 1);
            float a0 = acc[mt][nt][0] + bi0, a1 = acc[mt][nt][1] + bi1;
            float a2 = acc[mt][nt][2] + bi0, a3 = acc[mt][nt][3] + bi1;
            float* base0 = g_yc + (size_t)(b * CC + oc) * HP * HP;
            float* base1 = g_yc + (size_t)(b * CC + oc + 1) * HP * HP;
            if (v0) { base0[mq0 * HP + nq0] = a0; base1[mq0 * HP + nq0] = a1; }
            if (v1) { base0[mq1 * HP + nq1] = a2; base1[mq1 * HP + nq1] = a3; }
            if (nt < 4) {
                s00 = fmaf(a0, a0, s00); s00 = fmaf(a1, a1, s00);
                s10 = fmaf(a2, a2, s10); s10 = fmaf(a3, a3, s10);
            } else {
                s01 = fmaf(a0, a0, s01); s01 = fmaf(a1, a1, s01);
                s11 = fmaf(a2, a2, s11); s11 = fmaf(a3, a3, s11);
            }
        }
        s00 += __shfl_xor_sync(0xffffffffu, s00, 1);
        s00 += __shfl_xor_sync(0xffffffffu, s00, 2);
        s01 += __shfl_xor_sync(0xffffffffu, s01, 1);
        s01 += __shfl_xor_sync(0xffffffffu, s01, 2);
        s10 += __shfl_xor_sync(0xffffffffu, s10, 1);
        s10 += __shfl_xor_sync(0xffffffffu, s10, 2);
        s11 += __shfl_xor_sync(0xffffffffu, s11, 1);
        s11 += __shfl_xor_sync(0xffffffffu, s11, 2);
        if (t == 0) {
            float* ny0 = g_ny + (size_t)(b * NG + wn * 2) * HP * HP;
            float* ny1 = g_ny + (size_t)(b * NG + wn * 2 + 1) * HP * HP;
            if (v0) { ny0[mq0 * HP + nq0] = sqrtf(s00); ny1[mq0 * HP + nq0] = sqrtf(s01); }
            if (v1) { ny0[mq1 * HP + nq1] = sqrtf(s10); ny1[mq1 * HP + nq1] = sqrtf(s11); }
        }
    }
}

// ---------------- 81-offset correlation: 4-px register blocking ------------------
#define CSTRIDE 648                     // floats per channel block
#define CORR_SY (CG * CSTRIDE)
#define CORR_SN (16 * 40)
#define CORR_SMEM ((CORR_SY + CORR_SN) * 4)   // 85504 B

__global__ void __launch_bounds__(256, 2)
corr_kernel(float* __restrict__ out) {
    extern __shared__ float smc[];
    float* sy = smc;
    float* sn = smc + CORR_SY;

    int bg = blockIdx.z;
    int b  = bg >> 2, g = bg & 3;
    int i0 = blockIdx.y * 8;
    int j0 = blockIdx.x * 32;
    int tid = threadIdx.x;

    const float* ycb = g_yc + ((size_t)b * CC + g * CG) * HP * HP;
    for (int e = tid; e < CG * 16 * 40; e += 256) {
        int col = e % 40;
        int row = (e / 40) % 16;
        int c   = e / 640;
        sy[c * CSTRIDE + row * 40 + col] =
            ycb[(size_t)c * HP * HP + (i0 + row) * HP + (j0 + col)];
    }
    const float* nyb = g_ny + (size_t)bg * HP * HP;
    for (int e = tid; e < 16 * 40; e += 256) {
        int col = e % 40, row = e / 40;
        sn[e] = 1.0f / fmaxf(nyb[(i0 + row) * HP + (j0 + col)], EPSV);
    }
    __syncthreads();

    int sl  = tid & 3;
    int pos = tid >> 2;
    int ti  = pos >> 3;
    int tj4 = (pos & 7) * 4;

    float4 xv[8];
    const float* xsb = g_xs + ((size_t)(b * CC + g * CG + sl)) * (HS * HS)
                            + (i0 + ti) * HS + (j0 + tj4);
    #pragma unroll
    for (int cc = 0; cc < 8; cc++)
        xv[cc] = *(const float4*)(xsb + (size_t)(cc * 4) * HS * HS);

    float4 nx4 = *(const float4*)(g_nx + (size_t)bg * HS * HS
                                  + (i0 + ti) * HS + (j0 + tj4));
    float inx[4] = {1.0f / nx4.x, 1.0f / nx4.y, 1.0f / nx4.z, 1.0f / nx4.w};

    float* outp = out + (size_t)bg * NOFF * (HS * HS)
                      + (i0 + ti) * HS + (j0 + tj4);

    #pragma unroll 1
    for (int oi = 0; oi < 9; oi++) {
        float acc[9][4];
        #pragma unroll
        for (int oj = 0; oj < 9; oj++)
            #pragma unroll
            for (int p = 0; p < 4; p++) acc[oj][p] = 0.f;

        #pragma unroll
        for (int cc = 0; cc < 8; cc++) {
            const float* rp = sy + (4 * cc + sl) * CSTRIDE + (ti + oi) * 40 + tj4;
            float4 v0 = *(const float4*)(rp);
            float4 v1 = *(const float4*)(rp + 4);
            float4 v2 = *(const float4*)(rp + 8);
            float v[12] = {v0.x, v0.y, v0.z, v0.w, v1.x, v1.y, v1.z, v1.w,
                           v2.x, v2.y, v2.z, v2.w};
            float xp[4] = {xv[cc].x, xv[cc].y, xv[cc].z, xv[cc].w};
            #pragma unroll
            for (int oj = 0; oj < 9; oj++)
                #pragma unroll
                for (int p = 0; p < 4; p++)
                    acc[oj][p] = fmaf(xp[p], v[oj + p], acc[oj][p]);
        }

        #pragma unroll
        for (int oj = 0; oj < 9; oj++)
            #pragma unroll
            for (int p = 0; p < 4; p++) {
                float sv = acc[oj][p];
                sv += __shfl_xor_sync(0xffffffffu, sv, 1);
                sv += __shfl_xor_sync(0xffffffffu, sv, 2);
                acc[oj][p] = sv;
            }

        if (sl == 0) {
            const float* np_ = sn + (ti + oi) * 40 + tj4;
            float nv[12];
            #pragma unroll
            for (int q = 0; q < 3; q++) {
                float4 t4 = *(const float4*)(np_ + q * 4);
                nv[q*4] = t4.x; nv[q*4+1] = t4.y; nv[q*4+2] = t4.z; nv[q*4+3] = t4.w;
            }
            #pragma unroll
            for (int oj = 0; oj < 9; oj++) {
                float4 o4;
                o4.x = acc[oj][0] * inx[0] * nv[oj + 0];
                o4.y = acc[oj][1] * inx[1] * nv[oj + 1];
                o4.z = acc[oj][2] * inx[2] * nv[oj + 2];
                o4.w = acc[oj][3] * inx[3] * nv[oj + 3];
                *(float4*)(outp + (size_t)(oi * 9 + oj) * (HS * HS)) = o4;
            }
        }
    }
}

// ---------------- launcher --------------------------------------------------------
extern "C" void kernel_launch(void* const* d_in, const int* in_sizes, int n_in,
                              void* d_out, int out_size) {
    const float* x     = (const float*)d_in[0];
    const float* y     = (const float*)d_in[1];
    const float* Wt    = (const float*)d_in[2];
    const float* bconv = (const float*)d_in[3];
    float* out = (float*)d_out;

    cudaFuncSetAttribute(conv_mma_kernel,
                         cudaFuncAttributeMaxDynamicSharedMemorySize, CONV_SMEM);
    cudaFuncSetAttribute(corr_kernel,
                         cudaFuncAttributeMaxDynamicSharedMemorySize, CORR_SMEM);

    downsample_x_kernel<<<(BB*4*HS*HS) / 256, 256>>>(x);
    make_P_kernel<<<(BB*4*PROW + 255) / 256, 256>>>(y);
    prep_w_kernel<<<(32*128*16 + 255) / 256, 256>>>(Wt);
    conv_mma_kernel<<<dim3((NPIX + 127) / 128, BB), 256, CONV_SMEM>>>(bconv);
    corr_kernel<<<dim3(4, 16, BB * NG), 256, CORR_SMEM>>>(out);
}